// round 15
// baseline (speedup 1.0000x reference)
#include <cuda_runtime.h>
#include <cuda_bf16.h>
#include <cstdint>
#include <math.h>

#define CAP_E 655360
#define CAP_N 20004
#define CAP_V 100352

// Scratch (allocation-free rule: __device__ globals)
// preA/preB rows: 32 u32 of bf16x2, PERMUTED pair order (see R10):
//   storage s = tig*8 + nc  holds logical col-pair l = nc*4 + tig.
__device__ uint32_t g_preA[(size_t)CAP_V * 32];
__device__ uint32_t g_preB[(size_t)CAP_N * 32];
__device__ float g_ex[CAP_E];
__device__ int   g_starts[CAP_N];

// lower half <- lo, upper half <- hi
__device__ __forceinline__ uint32_t pack_bf2(float lo, float hi) {
    uint32_t r;
    asm("cvt.rn.bf16x2.f32 %0, %1, %2;" : "=r"(r) : "f"(hi), "f"(lo));
    return r;
}
// bf16x2: relu(a + b)
__device__ __forceinline__ uint32_t hadd_relu2(uint32_t a, uint32_t b) {
    __nv_bfloat162 av = *reinterpret_cast<__nv_bfloat162*>(&a);
    __nv_bfloat162 bv = *reinterpret_cast<__nv_bfloat162*>(&b);
    __nv_bfloat162 z = __float2bfloat162_rn(0.0f);
    __nv_bfloat162 r = __hmax2(__hadd2(av, bv), z);
    return *reinterpret_cast<uint32_t*>(&r);
}
__device__ __forceinline__ void mma_16816(float* c, uint32_t a0, uint32_t a1,
                                          uint32_t a2, uint32_t a3,
                                          uint32_t b0, uint32_t b1) {
    asm volatile(
        "mma.sync.aligned.m16n8k16.row.col.f32.bf16.bf16.f32 "
        "{%0,%1,%2,%3}, {%4,%5,%6,%7}, {%8,%9}, {%0,%1,%2,%3};"
        : "+f"(c[0]), "+f"(c[1]), "+f"(c[2]), "+f"(c[3])
        : "r"(a0), "r"(a1), "r"(a2), "r"(a3), "r"(b0), "r"(b1));
}

// ---------------------------------------------------------------------------
// Kernel 1 (HMMA): preA[v] = u2e[v]@W1a + b1 ; preB[n] = u2e[nodes[n]]@W1b
// Also computes g_starts (overlapped). Software pipeline depth 2.
// (Byte-identical to R14 pre_mma_kernel.)
// ---------------------------------------------------------------------------
__global__ __launch_bounds__(256) void pre_mma_kernel(
    const int* __restrict__ nodes, const int* __restrict__ seg,
    const float* __restrict__ u2e,
    const float* __restrict__ w1, const float* __restrict__ b1,
    int V, int N, int E)
{
    __shared__ float s_w1[8192];
    __shared__ uint2 s_frag[2048];
    __shared__ float s_b1[64];

    const int tid  = threadIdx.x;
    const int lane = tid & 31;
    const int wid  = tid >> 5;
    const int g    = lane >> 2;
    const int tig  = lane & 3;

    {
        int gtid = blockIdx.x * 256 + tid;
        if (gtid <= N) {
            if (gtid == N) g_starts[N] = E;
            else {
                int lo = 0, hi = E;
                while (lo < hi) {
                    int mid = (lo + hi) >> 1;
                    if (seg[mid] < gtid) lo = mid + 1; else hi = mid;
                }
                g_starts[gtid] = lo;
            }
        }
    }

    const float4* w1v = (const float4*)w1;
    for (int i = tid; i < 2048; i += 256) ((float4*)s_w1)[i] = w1v[i];
    if (tid < 64) s_b1[tid] = b1[tid];
    __syncthreads();

    for (int i = tid; i < 2048; i += 256) {
        int half = i >> 10;
        int rem  = i & 1023;
        int kc   = rem >> 8;
        int nc   = (rem >> 5) & 7;
        int ln   = rem & 31;
        int lg   = ln >> 2, lt = ln & 3;
        int k0 = 16 * lt + 4 * kc;
        int n  = nc * 8 + lg;
        const float* base = s_w1 + half * 4096;
        uint2 f;
        f.x = pack_bf2(base[k0 * 64 + n],       base[(k0 + 1) * 64 + n]);
        f.y = pack_bf2(base[(k0 + 2) * 64 + n], base[(k0 + 3) * 64 + n]);
        s_frag[i] = f;
    }
    __syncthreads();

    const int tA = (V + 15) / 16;
    const int tB = (N + 15) / 16;
    const int nw = gridDim.x * 8;
    const int w  = blockIdx.x * 8 + wid;
    int wA = (int)(((long long)nw * tA) / (tA + tB));
    if (wA < 1) wA = 1;
    if (wA > nw - 1) wA = nw - 1;

    const bool isA   = (w < wA);
    const int tiles  = isA ? tA : tB;
    const int tfirst = isA ? w : (w - wA);
    const int tstep  = isA ? wA : (nw - wA);
    const int rows   = isA ? V : N;
    uint32_t* gout   = isA ? g_preA : g_preB;
    const uint2* frag = s_frag + (isA ? 0 : 1024) + lane;

    if (tfirst >= tiles) return;

    float4 F0[4], F1[4];
    int r0 = tfirst * 16 + g;
    int r1 = r0 + 8;
    {
        const int rr0 = r0 < rows ? r0 : rows - 1;
        const int rr1 = r1 < rows ? r1 : rows - 1;
        const int src0 = isA ? rr0 : nodes[rr0];
        const int src1 = isA ? rr1 : nodes[rr1];
        const float4* x0 = (const float4*)(u2e + (size_t)src0 * 64) + tig * 4;
        const float4* x1 = (const float4*)(u2e + (size_t)src1 * 64) + tig * 4;
        #pragma unroll
        for (int q = 0; q < 4; q++) { F0[q] = x0[q]; F1[q] = x1[q]; }
    }

    for (int t = tfirst; t < tiles; t += tstep) {
        uint32_t a0v[4], a1v[4], a2v[4], a3v[4];
        #pragma unroll
        for (int kc = 0; kc < 4; kc++) {
            a0v[kc] = pack_bf2(F0[kc].x, F0[kc].y);
            a1v[kc] = pack_bf2(F1[kc].x, F1[kc].y);
            a2v[kc] = pack_bf2(F0[kc].z, F0[kc].w);
            a3v[kc] = pack_bf2(F1[kc].z, F1[kc].w);
        }

        const int tn = t + tstep;
        if (tn < tiles) {
            const int nr0 = tn * 16 + g;
            const int nr1 = nr0 + 8;
            const int rr0 = nr0 < rows ? nr0 : rows - 1;
            const int rr1 = nr1 < rows ? nr1 : rows - 1;
            const int src0 = isA ? rr0 : nodes[rr0];
            const int src1 = isA ? rr1 : nodes[rr1];
            const float4* x0 = (const float4*)(u2e + (size_t)src0 * 64) + tig * 4;
            const float4* x1 = (const float4*)(u2e + (size_t)src1 * 64) + tig * 4;
            #pragma unroll
            for (int q = 0; q < 4; q++) { F0[q] = x0[q]; F1[q] = x1[q]; }
        }

        float c[8][4];
        #pragma unroll
        for (int nc = 0; nc < 8; nc++) {
            c[nc][0] = 0.f; c[nc][1] = 0.f; c[nc][2] = 0.f; c[nc][3] = 0.f;
        }

        #pragma unroll
        for (int kc = 0; kc < 4; kc++) {
            #pragma unroll
            for (int nc = 0; nc < 8; nc++) {
                uint2 b = frag[(kc * 8 + nc) * 32];
                mma_16816(c[nc], a0v[kc], a1v[kc], a2v[kc], a3v[kc], b.x, b.y);
            }
        }

        uint32_t o0[8], o1[8];
        #pragma unroll
        for (int nc = 0; nc < 8; nc++) {
            const int col0 = nc * 8 + 2 * tig;
            const float add0 = isA ? s_b1[col0] : 0.0f;
            const float add1 = isA ? s_b1[col0 + 1] : 0.0f;
            o0[nc] = pack_bf2(c[nc][0] + add0, c[nc][1] + add1);
            o1[nc] = pack_bf2(c[nc][2] + add0, c[nc][3] + add1);
        }
        if (r0 < rows) {
            uint4* p = (uint4*)(gout + (size_t)r0 * 32 + tig * 8);
            p[0] = ((uint4*)o0)[0]; p[1] = ((uint4*)o0)[1];
        }
        if (r1 < rows) {
            uint4* p = (uint4*)(gout + (size_t)r1 * 32 + tig * 8);
            p[0] = ((uint4*)o1)[0]; p[1] = ((uint4*)o1)[1];
        }
        r0 = tn * 16 + g;
        r1 = r0 + 8;
    }
}

// ---------------------------------------------------------------------------
// Kernel 2 (fused, node-centric): warp per node.
// Phase 1: tiles of 16 edges of THIS node:
//   A = relu(preA[neigh] + preB[node])  (preB loaded ONCE per node)
//   H2 via HMMA; ex = exp(logit); segment-sum accumulated inline; ex -> g_ex.
// Phase 2: out[node] = (1/sum) * Σ ex_i * u2e[neigh_i]  (R13 agg pass-2 form).
// W2 fragments in SMEM to keep regs <= 128 at 2 CTAs/SM. Persistent grid.
// ---------------------------------------------------------------------------
__global__ __launch_bounds__(256, 2) void fused_kernel(
    const int* __restrict__ neigh, const float* __restrict__ u2e,
    const float* __restrict__ w2, const float* __restrict__ b2,
    const float* __restrict__ w3, const float* __restrict__ b3,
    float* __restrict__ out, int N, int E)
{
    __shared__ float s_w2[4096];
    __shared__ uint2 s_frag[1024];
    __shared__ float s_b2[64];
    __shared__ float s_w3[64];
    __shared__ float s_b3;

    const int tid  = threadIdx.x;
    const int lane = tid & 31;
    const int wid  = tid >> 5;
    const int g    = lane >> 2;
    const int tig  = lane & 3;

    const float4* w2v = (const float4*)w2;
    for (int i = tid; i < 1024; i += 256) ((float4*)s_w2)[i] = w2v[i];
    if (tid < 64) { s_b2[tid] = b2[tid]; s_w3[tid] = w3[tid]; }
    if (tid == 255) s_b3 = b3[0];
    __syncthreads();

    // Standard m16n8k16 B fragments (logical k order) -> SMEM.
    for (int i = tid; i < 1024; i += 256) {
        int kc = i >> 8;
        int nc = (i >> 5) & 7;
        int ln = i & 31;
        int lg = ln >> 2, lt = ln & 3;
        int k0 = kc * 16 + 2 * lt;
        int n  = nc * 8 + lg;
        uint2 f;
        f.x = pack_bf2(s_w2[k0 * 64 + n],       s_w2[(k0 + 1) * 64 + n]);
        f.y = pack_bf2(s_w2[(k0 + 8) * 64 + n], s_w2[(k0 + 9) * 64 + n]);
        s_frag[i] = f;
    }
    __syncthreads();

    const float vb3 = s_b3;
    const uint2* frag = s_frag + lane;
    const int warp_gid = blockIdx.x * 8 + wid;
    const int nwarps   = gridDim.x * 8;

    for (int gw = warp_gid; gw < N; gw += nwarps) {
        const int s    = g_starts[gw];
        const int epos = g_starts[gw + 1];
        const int deg  = epos - s;

        // this node's preB chunk (same for every edge row)
        uint4 Pb0, Pb1;
        {
            const uint4* pb = (const uint4*)(g_preB + (size_t)gw * 32) + tig * 2;
            Pb0 = pb[0]; Pb1 = pb[1];
        }

        // ---- phase 1: logits/ex for all edges of this node ----
        float sum = 0.0f;
        const int ntile = (deg + 15) >> 4;
        for (int t = 0; t < ntile; t++) {
            const int base = s + t * 16;
            const int e0 = base + g;
            const int e1 = e0 + 8;
            const int ee0 = e0 < epos ? e0 : epos - 1;
            const int ee1 = e1 < epos ? e1 : epos - 1;

            const uint4* qa0 = (const uint4*)(g_preA + (size_t)neigh[ee0] * 32) + tig * 2;
            const uint4* qa1 = (const uint4*)(g_preA + (size_t)neigh[ee1] * 32) + tig * 2;
            uint4 Aa0 = qa0[0], Ab0 = qa0[1];
            uint4 Aa1 = qa1[0], Ab1 = qa1[1];

            uint32_t r0[8], r1[8];
            r0[0] = hadd_relu2(Aa0.x, Pb0.x); r0[1] = hadd_relu2(Aa0.y, Pb0.y);
            r0[2] = hadd_relu2(Aa0.z, Pb0.z); r0[3] = hadd_relu2(Aa0.w, Pb0.w);
            r0[4] = hadd_relu2(Ab0.x, Pb1.x); r0[5] = hadd_relu2(Ab0.y, Pb1.y);
            r0[6] = hadd_relu2(Ab0.z, Pb1.z); r0[7] = hadd_relu2(Ab0.w, Pb1.w);
            r1[0] = hadd_relu2(Aa1.x, Pb0.x); r1[1] = hadd_relu2(Aa1.y, Pb0.y);
            r1[2] = hadd_relu2(Aa1.z, Pb0.z); r1[3] = hadd_relu2(Aa1.w, Pb0.w);
            r1[4] = hadd_relu2(Ab1.x, Pb1.x); r1[5] = hadd_relu2(Ab1.y, Pb1.y);
            r1[6] = hadd_relu2(Ab1.z, Pb1.z); r1[7] = hadd_relu2(Ab1.w, Pb1.w);

            float c[8][4];
            #pragma unroll
            for (int nc = 0; nc < 8; nc++) {
                c[nc][0] = 0.f; c[nc][1] = 0.f; c[nc][2] = 0.f; c[nc][3] = 0.f;
            }

            #pragma unroll
            for (int kc = 0; kc < 4; kc++) {
                uint32_t a0 = r0[2 * kc],     a2 = r0[2 * kc + 1];
                uint32_t a1 = r1[2 * kc],     a3 = r1[2 * kc + 1];
                #pragma unroll
                for (int nc = 0; nc < 8; nc++) {
                    uint2 b = frag[(kc * 8 + nc) * 32];
                    mma_16816(c[nc], a0, a1, a2, a3, b.x, b.y);
                }
            }

            float p0 = 0.f, p1 = 0.f;
            #pragma unroll
            for (int nc = 0; nc < 8; nc++) {
                const int col0 = nc * 8 + 2 * tig;
                const int col1 = col0 + 1;
                const float bb0 = s_b2[col0], bb1 = s_b2[col1];
                const float ww0 = s_w3[col0], ww1 = s_w3[col1];
                p0 = fmaf(fmaxf(c[nc][0] + bb0, 0.f), ww0, p0);
                p0 = fmaf(fmaxf(c[nc][1] + bb1, 0.f), ww1, p0);
                p1 = fmaf(fmaxf(c[nc][2] + bb0, 0.f), ww0, p1);
                p1 = fmaf(fmaxf(c[nc][3] + bb1, 0.f), ww1, p1);
            }
            p0 += __shfl_xor_sync(0xffffffffu, p0, 1);
            p0 += __shfl_xor_sync(0xffffffffu, p0, 2);
            p1 += __shfl_xor_sync(0xffffffffu, p1, 1);
            p1 += __shfl_xor_sync(0xffffffffu, p1, 2);

            if (tig == 0) {
                float ex0 = 0.f, ex1 = 0.f;
                if (e0 < epos) { ex0 = __expf(p0 + vb3); g_ex[e0] = ex0; }
                if (e1 < epos) { ex1 = __expf(p1 + vb3); g_ex[e1] = ex1; }
                sum += ex0 + ex1;
            }
        }

        // reduce sum (only tig==0 lanes contributed; others hold 0)
        #pragma unroll
        for (int o = 16; o; o >>= 1) sum += __shfl_xor_sync(0xffffffffu, sum, o);
        const float inv = 1.0f / fmaxf(sum, 1e-9f);
        __syncwarp();   // make g_ex stores visible warp-wide

        // ---- phase 2: weighted sum of u2e (R13 agg pass-2 form) ----
        const int half = lane >> 4;
        const int qc   = lane & 15;
        float4 acc0 = make_float4(0.f, 0.f, 0.f, 0.f);
        float4 acc1 = make_float4(0.f, 0.f, 0.f, 0.f);
        int i = s + half;
        for (; i + 2 < epos; i += 4) {
            float att0 = g_ex[i] * inv;
            float att1 = g_ex[i + 2] * inv;
            float4 v0 = ((const float4*)(u2e + (size_t)neigh[i] * 64))[qc];
            float4 v1 = ((const float4*)(u2e + (size_t)neigh[i + 2] * 64))[qc];
            acc0.x = fmaf(att0, v0.x, acc0.x);
            acc0.y = fmaf(att0, v0.y, acc0.y);
            acc0.z = fmaf(att0, v0.z, acc0.z);
            acc0.w = fmaf(att0, v0.w, acc0.w);
            acc1.x = fmaf(att1, v1.x, acc1.x);
            acc1.y = fmaf(att1, v1.y, acc1.y);
            acc1.z = fmaf(att1, v1.z, acc1.z);
            acc1.w = fmaf(att1, v1.w, acc1.w);
        }
        if (i < epos) {
            float att = g_ex[i] * inv;
            float4 v = ((const float4*)(u2e + (size_t)neigh[i] * 64))[qc];
            acc0.x = fmaf(att, v.x, acc0.x);
            acc0.y = fmaf(att, v.y, acc0.y);
            acc0.z = fmaf(att, v.z, acc0.z);
            acc0.w = fmaf(att, v.w, acc0.w);
        }
        acc0.x += acc1.x; acc0.y += acc1.y; acc0.z += acc1.z; acc0.w += acc1.w;
        acc0.x += __shfl_xor_sync(0xffffffffu, acc0.x, 16);
        acc0.y += __shfl_xor_sync(0xffffffffu, acc0.y, 16);
        acc0.z += __shfl_xor_sync(0xffffffffu, acc0.z, 16);
        acc0.w += __shfl_xor_sync(0xffffffffu, acc0.w, 16);
        if (lane < 16)
            ((float4*)out)[(size_t)gw * 16 + qc] = acc0;
    }
}

// ---------------------------------------------------------------------------
extern "C" void kernel_launch(void* const* d_in, const int* in_sizes, int n_in,
                              void* d_out, int out_size)
{
    const int*   nodes = (const int*)d_in[0];
    const int*   neigh = (const int*)d_in[1];
    const int*   seg   = (const int*)d_in[2];
    const float* u2e   = (const float*)d_in[3];
    const float* w1    = (const float*)d_in[4];
    const float* b1    = (const float*)d_in[5];
    const float* w2    = (const float*)d_in[6];
    const float* b2    = (const float*)d_in[7];
    const float* w3    = (const float*)d_in[8];
    const float* b3    = (const float*)d_in[9];

    int N = in_sizes[0];
    int E = in_sizes[1];
    int V = in_sizes[3] / 64;
    if (E > CAP_E) E = CAP_E;
    if (N > CAP_N - 2) N = CAP_N - 2;
    if (V > CAP_V) V = CAP_V;

    int pre_tiles = (V + 15) / 16 + (N + 15) / 16;
    int pre_grid = (pre_tiles + 7) / 8;
    if (pre_grid > 296) pre_grid = 296;
    pre_mma_kernel<<<pre_grid, 256>>>(nodes, seg, u2e, w1, b1, V, N, E);

    int fgrid = (N + 7) / 8;
    if (fgrid > 296) fgrid = 296;
    fused_kernel<<<fgrid, 256>>>(neigh, u2e, w2, b2, w3, b3,
                                 (float*)d_out, N, E);
}

// round 16
// speedup vs baseline: 1.1271x; 1.1271x over previous
#include <cuda_runtime.h>
#include <cuda_bf16.h>
#include <cstdint>
#include <math.h>

#define CAP_E 655360
#define CAP_N 20004
#define CAP_V 100352

// Scratch (allocation-free rule: __device__ globals)
// preA/preB rows: 32 u32 of bf16x2, PERMUTED pair order (see R10):
//   storage s = tig*8 + nc  holds logical col-pair l = nc*4 + tig.
__device__ uint32_t g_preA[(size_t)CAP_V * 32];
__device__ uint32_t g_preB[(size_t)CAP_N * 32];
__device__ float g_ex[CAP_E];       // exp(logit) written directly by edge
__device__ int   g_starts[CAP_N];

// lower half <- lo, upper half <- hi
__device__ __forceinline__ uint32_t pack_bf2(float lo, float hi) {
    uint32_t r;
    asm("cvt.rn.bf16x2.f32 %0, %1, %2;" : "=r"(r) : "f"(hi), "f"(lo));
    return r;
}
// bf16x2: relu(a + b)
__device__ __forceinline__ uint32_t hadd_relu2(uint32_t a, uint32_t b) {
    __nv_bfloat162 av = *reinterpret_cast<__nv_bfloat162*>(&a);
    __nv_bfloat162 bv = *reinterpret_cast<__nv_bfloat162*>(&b);
    __nv_bfloat162 z = __float2bfloat162_rn(0.0f);
    __nv_bfloat162 r = __hmax2(__hadd2(av, bv), z);
    return *reinterpret_cast<uint32_t*>(&r);
}
__device__ __forceinline__ void mma_16816(float* c, uint32_t a0, uint32_t a1,
                                          uint32_t a2, uint32_t a3,
                                          uint32_t b0, uint32_t b1) {
    asm volatile(
        "mma.sync.aligned.m16n8k16.row.col.f32.bf16.bf16.f32 "
        "{%0,%1,%2,%3}, {%4,%5,%6,%7}, {%8,%9}, {%0,%1,%2,%3};"
        : "+f"(c[0]), "+f"(c[1]), "+f"(c[2]), "+f"(c[3])
        : "r"(a0), "r"(a1), "r"(a2), "r"(a3), "r"(b0), "r"(b1));
}

// ---------------------------------------------------------------------------
// pre helpers: load one tile's rows / compute+store one tile.
// ---------------------------------------------------------------------------
__device__ __forceinline__ void pre_load_tile(
    float4* F0, float4* F1, int t, int rows, bool isA,
    const int* __restrict__ nodes, const float* __restrict__ u2e,
    int g, int tig)
{
    const int r0 = t * 16 + g;
    const int r1 = r0 + 8;
    const int rr0 = r0 < rows ? r0 : rows - 1;
    const int rr1 = r1 < rows ? r1 : rows - 1;
    const int src0 = isA ? rr0 : nodes[rr0];
    const int src1 = isA ? rr1 : nodes[rr1];
    const float4* x0 = (const float4*)(u2e + (size_t)src0 * 64) + tig * 4;
    const float4* x1 = (const float4*)(u2e + (size_t)src1 * 64) + tig * 4;
    #pragma unroll
    for (int q = 0; q < 4; q++) { F0[q] = x0[q]; F1[q] = x1[q]; }
}

// Convert F -> frags, optionally prefetch tile tpf into the SAME F buffer
// (overlaps the MMA below), run MMA, store permuted-pair epilogue.
__device__ __forceinline__ void pre_process_tile(
    float4* F0, float4* F1, int t, int tpf, int tiles, int rows, bool isA,
    const int* __restrict__ nodes, const float* __restrict__ u2e,
    const uint2* __restrict__ frag, const float* __restrict__ s_b1,
    uint32_t* __restrict__ gout, int g, int tig)
{
    uint32_t a0v[4], a1v[4], a2v[4], a3v[4];
    #pragma unroll
    for (int kc = 0; kc < 4; kc++) {
        a0v[kc] = pack_bf2(F0[kc].x, F0[kc].y);
        a1v[kc] = pack_bf2(F1[kc].x, F1[kc].y);
        a2v[kc] = pack_bf2(F0[kc].z, F0[kc].w);
        a3v[kc] = pack_bf2(F1[kc].z, F1[kc].w);
    }

    if (tpf < tiles)
        pre_load_tile(F0, F1, tpf, rows, isA, nodes, u2e, g, tig);

    float c[8][4];
    #pragma unroll
    for (int nc = 0; nc < 8; nc++) {
        c[nc][0] = 0.f; c[nc][1] = 0.f; c[nc][2] = 0.f; c[nc][3] = 0.f;
    }
    #pragma unroll
    for (int kc = 0; kc < 4; kc++) {
        #pragma unroll
        for (int nc = 0; nc < 8; nc++) {
            uint2 b = frag[(kc * 8 + nc) * 32];
            mma_16816(c[nc], a0v[kc], a1v[kc], a2v[kc], a3v[kc], b.x, b.y);
        }
    }

    uint32_t o0[8], o1[8];
    #pragma unroll
    for (int nc = 0; nc < 8; nc++) {
        const int col0 = nc * 8 + 2 * tig;
        const float add0 = isA ? s_b1[col0] : 0.0f;
        const float add1 = isA ? s_b1[col0 + 1] : 0.0f;
        o0[nc] = pack_bf2(c[nc][0] + add0, c[nc][1] + add1);
        o1[nc] = pack_bf2(c[nc][2] + add0, c[nc][3] + add1);
    }
    const int r0 = t * 16 + g;
    const int r1 = r0 + 8;
    if (r0 < rows) {
        uint4* p = (uint4*)(gout + (size_t)r0 * 32 + tig * 8);
        p[0] = ((uint4*)o0)[0]; p[1] = ((uint4*)o0)[1];
    }
    if (r1 < rows) {
        uint4* p = (uint4*)(gout + (size_t)r1 * 32 + tig * 8);
        p[0] = ((uint4*)o1)[0]; p[1] = ((uint4*)o1)[1];
    }
}

// ---------------------------------------------------------------------------
// Kernel 1 (HMMA): preA[v] = u2e[v]@W1a + b1 ; preB[n] = u2e[nodes[n]]@W1b
// Also computes g_starts (overlapped). Software pipeline depth 3: TWO tiles
// of row loads in flight (double-buffered F regs, prefetch distance 2).
// ---------------------------------------------------------------------------
__global__ __launch_bounds__(256) void pre_mma_kernel(
    const int* __restrict__ nodes, const int* __restrict__ seg,
    const float* __restrict__ u2e,
    const float* __restrict__ w1, const float* __restrict__ b1,
    int V, int N, int E)
{
    __shared__ float s_w1[8192];      // full W1 [128][64] fp32 stage (32 KB)
    __shared__ uint2 s_frag[2048];    // [half][kc][nc][lane] bf16 frags (16 KB)
    __shared__ float s_b1[64];

    const int tid  = threadIdx.x;
    const int lane = tid & 31;
    const int wid  = tid >> 5;
    const int g    = lane >> 2;
    const int tig  = lane & 3;

    // Overlapped: per-node edge-range starts via binary search on sorted seg.
    {
        int gtid = blockIdx.x * 256 + tid;
        if (gtid <= N) {
            if (gtid == N) g_starts[N] = E;
            else {
                int lo = 0, hi = E;
                while (lo < hi) {
                    int mid = (lo + hi) >> 1;
                    if (seg[mid] < gtid) lo = mid + 1; else hi = mid;
                }
                g_starts[gtid] = lo;
            }
        }
    }

    const float4* w1v = (const float4*)w1;
    for (int i = tid; i < 2048; i += 256) ((float4*)s_w1)[i] = w1v[i];
    if (tid < 64) s_b1[tid] = b1[tid];
    __syncthreads();

    // bf16 fragment table for both W1 halves, with permuted k rows.
    for (int i = tid; i < 2048; i += 256) {
        int half = i >> 10;
        int rem  = i & 1023;
        int kc   = rem >> 8;
        int nc   = (rem >> 5) & 7;
        int ln   = rem & 31;
        int lg   = ln >> 2, lt = ln & 3;
        int k0 = 16 * lt + 4 * kc;
        int n  = nc * 8 + lg;
        const float* base = s_w1 + half * 4096;
        uint2 f;
        f.x = pack_bf2(base[k0 * 64 + n],       base[(k0 + 1) * 64 + n]);
        f.y = pack_bf2(base[(k0 + 2) * 64 + n], base[(k0 + 3) * 64 + n]);
        s_frag[i] = f;
    }
    __syncthreads();

    const int tA = (V + 15) / 16;
    const int tB = (N + 15) / 16;
    const int nw = gridDim.x * 8;
    const int w  = blockIdx.x * 8 + wid;
    int wA = (int)(((long long)nw * tA) / (tA + tB));
    if (wA < 1) wA = 1;
    if (wA > nw - 1) wA = nw - 1;

    const bool isA   = (w < wA);
    const int tiles  = isA ? tA : tB;
    const int tfirst = isA ? w : (w - wA);
    const int tstep  = isA ? wA : (nw - wA);
    const int rows   = isA ? V : N;
    uint32_t* gout   = isA ? g_preA : g_preB;
    const uint2* frag = s_frag + (isA ? 0 : 1024) + lane;

    if (tfirst >= tiles) return;

    // Preamble: two tiles in flight.
    float4 Xa0[4], Xa1[4], Xb0[4], Xb1[4];
    pre_load_tile(Xa0, Xa1, tfirst, rows, isA, nodes, u2e, g, tig);
    if (tfirst + tstep < tiles)
        pre_load_tile(Xb0, Xb1, tfirst + tstep, rows, isA, nodes, u2e, g, tig);

    bool use_a = true;
    for (int t = tfirst; t < tiles; t += tstep) {
        const int tpf = t + 2 * tstep;
        if (use_a)
            pre_process_tile(Xa0, Xa1, t, tpf, tiles, rows, isA,
                             nodes, u2e, frag, s_b1, gout, g, tig);
        else
            pre_process_tile(Xb0, Xb1, t, tpf, tiles, rows, isA,
                             nodes, u2e, frag, s_b1, gout, g, tig);
        use_a = !use_a;
    }
}

// ---------------------------------------------------------------------------
// Kernel 2 (HMMA): A[16,64] = relu(preA_bf[neigh] + preB_bf[seg]);
// H2 = A @ W2_bf16 ; stores ex[e] = exp(logit) directly.  (R14 form)
// ---------------------------------------------------------------------------
__global__ __launch_bounds__(256, 2) void edge_mma_kernel(
    const int* __restrict__ neigh, const int* __restrict__ seg,
    const float* __restrict__ w2, const float* __restrict__ b2,
    const float* __restrict__ w3, const float* __restrict__ b3,
    int E, int ntiles)
{
    __shared__ float s_w2[4096];
    __shared__ float s_b2[64];
    __shared__ float s_w3[64];
    __shared__ float s_b3;

    const int tid  = threadIdx.x;
    const int lane = tid & 31;
    const int wid  = tid >> 5;
    const int g    = lane >> 2;
    const int tig  = lane & 3;

    const float4* w2v = (const float4*)w2;
    for (int i = tid; i < 1024; i += 256) ((float4*)s_w2)[i] = w2v[i];
    if (tid < 64) { s_b2[tid] = b2[tid]; s_w3[tid] = w3[tid]; }
    if (tid == 255) s_b3 = b3[0];
    __syncthreads();

    uint32_t Bf[4][8][2];
    #pragma unroll
    for (int kc = 0; kc < 4; kc++) {
        int k0 = kc * 16 + 2 * tig;
        #pragma unroll
        for (int nc = 0; nc < 8; nc++) {
            int n = nc * 8 + g;
            Bf[kc][nc][0] = pack_bf2(s_w2[k0 * 64 + n],       s_w2[(k0 + 1) * 64 + n]);
            Bf[kc][nc][1] = pack_bf2(s_w2[(k0 + 8) * 64 + n], s_w2[(k0 + 9) * 64 + n]);
        }
    }
    const float vb3 = s_b3;

    const int warp_gid = blockIdx.x * 8 + wid;
    const int nwarps   = gridDim.x * 8;

    for (int tile = warp_gid; tile < ntiles; tile += nwarps) {
        const int base = tile * 16;
        const int e0 = base + g;
        const int e1 = e0 + 8;
        const int ee0 = e0 < E ? e0 : E - 1;
        const int ee1 = e1 < E ? e1 : E - 1;

        const uint4* qa0 = (const uint4*)(g_preA + (size_t)neigh[ee0] * 32) + tig * 2;
        const uint4* qb0 = (const uint4*)(g_preB + (size_t)seg[ee0]  * 32) + tig * 2;
        const uint4* qa1 = (const uint4*)(g_preA + (size_t)neigh[ee1] * 32) + tig * 2;
        const uint4* qb1 = (const uint4*)(g_preB + (size_t)seg[ee1]  * 32) + tig * 2;

        uint4 Aa0 = qa0[0], Ab0 = qa0[1];
        uint4 Ba0 = qb0[0], Bb0 = qb0[1];
        uint4 Aa1 = qa1[0], Ab1 = qa1[1];
        uint4 Ba1 = qb1[0], Bb1 = qb1[1];

        uint32_t r0[8], r1[8];
        r0[0] = hadd_relu2(Aa0.x, Ba0.x); r0[1] = hadd_relu2(Aa0.y, Ba0.y);
        r0[2] = hadd_relu2(Aa0.z, Ba0.z); r0[3] = hadd_relu2(Aa0.w, Ba0.w);
        r0[4] = hadd_relu2(Ab0.x, Bb0.x); r0[5] = hadd_relu2(Ab0.y, Bb0.y);
        r0[6] = hadd_relu2(Ab0.z, Bb0.z); r0[7] = hadd_relu2(Ab0.w, Bb0.w);
        r1[0] = hadd_relu2(Aa1.x, Ba1.x); r1[1] = hadd_relu2(Aa1.y, Ba1.y);
        r1[2] = hadd_relu2(Aa1.z, Ba1.z); r1[3] = hadd_relu2(Aa1.w, Ba1.w);
        r1[4] = hadd_relu2(Ab1.x, Bb1.x); r1[5] = hadd_relu2(Ab1.y, Bb1.y);
        r1[6] = hadd_relu2(Ab1.z, Bb1.z); r1[7] = hadd_relu2(Ab1.w, Bb1.w);

        float c[8][4];
        #pragma unroll
        for (int nc = 0; nc < 8; nc++) {
            c[nc][0] = 0.f; c[nc][1] = 0.f; c[nc][2] = 0.f; c[nc][3] = 0.f;
        }

        #pragma unroll
        for (int kc = 0; kc < 4; kc++) {
            uint32_t a0 = r0[2 * kc],     a2 = r0[2 * kc + 1];
            uint32_t a1 = r1[2 * kc],     a3 = r1[2 * kc + 1];
            #pragma unroll
            for (int nc = 0; nc < 8; nc++)
                mma_16816(c[nc], a0, a1, a2, a3, Bf[kc][nc][0], Bf[kc][nc][1]);
        }

        float p0 = 0.f, p1 = 0.f;
        #pragma unroll
        for (int nc = 0; nc < 8; nc++) {
            const int col0 = nc * 8 + 2 * tig;
            const int col1 = col0 + 1;
            const float bb0 = s_b2[col0], bb1 = s_b2[col1];
            const float ww0 = s_w3[col0], ww1 = s_w3[col1];
            p0 = fmaf(fmaxf(c[nc][0] + bb0, 0.f), ww0, p0);
            p0 = fmaf(fmaxf(c[nc][1] + bb1, 0.f), ww1, p0);
            p1 = fmaf(fmaxf(c[nc][2] + bb0, 0.f), ww0, p1);
            p1 = fmaf(fmaxf(c[nc][3] + bb1, 0.f), ww1, p1);
        }
        p0 += __shfl_xor_sync(0xffffffffu, p0, 1);
        p0 += __shfl_xor_sync(0xffffffffu, p0, 2);
        p1 += __shfl_xor_sync(0xffffffffu, p1, 1);
        p1 += __shfl_xor_sync(0xffffffffu, p1, 2);

        if (tig == 0) {
            if (e0 < E) g_ex[e0] = __expf(p0 + vb3);
            if (e1 < E) g_ex[e1] = __expf(p1 + vb3);
        }
    }
}

// ---------------------------------------------------------------------------
// Kernel 3: warp-per-node normalize + attention-weighted sum.  (R14 form)
// ---------------------------------------------------------------------------
__global__ void agg_kernel(const int* __restrict__ neigh,
                           const float* __restrict__ u2e,
                           float* __restrict__ out, int N, int E)
{
    int gw   = (blockIdx.x * blockDim.x + threadIdx.x) >> 5;
    int lane = threadIdx.x & 31;
    if (gw >= N) return;

    int s    = g_starts[gw];
    int epos = g_starts[gw + 1];

    // pass 1: segment sum of ex
    float sum = 0.0f;
    for (int i = s + lane; i < epos; i += 32) sum += g_ex[i];
    #pragma unroll
    for (int o = 16; o; o >>= 1) sum += __shfl_xor_sync(0xffffffffu, sum, o);
    float inv = 1.0f / fmaxf(sum, 1e-9f);

    // pass 2: half-warp per edge, float4 per lane, x2 unroll
    const int half = lane >> 4;
    const int qc   = lane & 15;
    float4 acc0 = make_float4(0.f, 0.f, 0.f, 0.f);
    float4 acc1 = make_float4(0.f, 0.f, 0.f, 0.f);
    int i = s + half;
    for (; i + 2 < epos; i += 4) {
        float att0 = g_ex[i] * inv;
        float att1 = g_ex[i + 2] * inv;
        float4 v0 = ((const float4*)(u2e + (size_t)neigh[i] * 64))[qc];
        float4 v1 = ((const float4*)(u2e + (size_t)neigh[i + 2] * 64))[qc];
        acc0.x = fmaf(att0, v0.x, acc0.x);
        acc0.y = fmaf(att0, v0.y, acc0.y);
        acc0.z = fmaf(att0, v0.z, acc0.z);
        acc0.w = fmaf(att0, v0.w, acc0.w);
        acc1.x = fmaf(att1, v1.x, acc1.x);
        acc1.y = fmaf(att1, v1.y, acc1.y);
        acc1.z = fmaf(att1, v1.z, acc1.z);
        acc1.w = fmaf(att1, v1.w, acc1.w);
    }
    if (i < epos) {
        float att = g_ex[i] * inv;
        float4 v = ((const float4*)(u2e + (size_t)neigh[i] * 64))[qc];
        acc0.x = fmaf(att, v.x, acc0.x);
        acc0.y = fmaf(att, v.y, acc0.y);
        acc0.z = fmaf(att, v.z, acc0.z);
        acc0.w = fmaf(att, v.w, acc0.w);
    }
    acc0.x += acc1.x; acc0.y += acc1.y; acc0.z += acc1.z; acc0.w += acc1.w;
    acc0.x += __shfl_xor_sync(0xffffffffu, acc0.x, 16);
    acc0.y += __shfl_xor_sync(0xffffffffu, acc0.y, 16);
    acc0.z += __shfl_xor_sync(0xffffffffu, acc0.z, 16);
    acc0.w += __shfl_xor_sync(0xffffffffu, acc0.w, 16);
    if (lane < 16)
        ((float4*)out)[(size_t)gw * 16 + qc] = acc0;
}

// ---------------------------------------------------------------------------
extern "C" void kernel_launch(void* const* d_in, const int* in_sizes, int n_in,
                              void* d_out, int out_size)
{
    const int*   nodes = (const int*)d_in[0];
    const int*   neigh = (const int*)d_in[1];
    const int*   seg   = (const int*)d_in[2];
    const float* u2e   = (const float*)d_in[3];
    const float* w1    = (const float*)d_in[4];
    const float* b1    = (const float*)d_in[5];
    const float* w2    = (const float*)d_in[6];
    const float* b2    = (const float*)d_in[7];
    const float* w3    = (const float*)d_in[8];
    const float* b3    = (const float*)d_in[9];

    int N = in_sizes[0];
    int E = in_sizes[1];
    int V = in_sizes[3] / 64;
    if (E > CAP_E) E = CAP_E;
    if (N > CAP_N - 2) N = CAP_N - 2;
    if (V > CAP_V) V = CAP_V;

    int pre_tiles = (V + 15) / 16 + (N + 15) / 16;
    int pre_grid = (pre_tiles + 7) / 8;
    if (pre_grid > 296) pre_grid = 296;
    pre_mma_kernel<<<pre_grid, 256>>>(nodes, seg, u2e, w1, b1, V, N, E);

    int ntiles = (E + 15) / 16;
    int grid = 296;
    int maxgrid = (ntiles + 7) / 8;
    if (grid > maxgrid) grid = maxgrid;
    edge_mma_kernel<<<grid, 256>>>(neigh, seg, w2, b2, w3, b3, E, ntiles);

    agg_kernel<<<(N * 32 + 255) / 256, 256>>>(neigh, u2e, (float*)d_out, N, E);
}

// round 17
// speedup vs baseline: 1.1850x; 1.0514x over previous
#include <cuda_runtime.h>
#include <cuda_bf16.h>
#include <cstdint>
#include <math.h>

#define CAP_E 655360
#define CAP_N 20004
#define CAP_V 100352

// Scratch (allocation-free rule: __device__ globals)
// preA/preB rows: 32 u32 of bf16x2, PERMUTED pair order (see R10):
//   storage s = tig*8 + nc  holds logical col-pair l = nc*4 + tig.
__device__ uint32_t g_preA[(size_t)CAP_V * 32];
__device__ uint32_t g_preB[(size_t)CAP_N * 32];
__device__ float g_ex[CAP_E];       // exp(logit) written by edge phase
__device__ int   g_starts[CAP_N];
__device__ unsigned int g_bar;      // monotonic device-wide barrier counter

// lower half <- lo, upper half <- hi
__device__ __forceinline__ uint32_t pack_bf2(float lo, float hi) {
    uint32_t r;
    asm("cvt.rn.bf16x2.f32 %0, %1, %2;" : "=r"(r) : "f"(hi), "f"(lo));
    return r;
}
// bf16x2: relu(a + b)
__device__ __forceinline__ uint32_t hadd_relu2(uint32_t a, uint32_t b) {
    __nv_bfloat162 av = *reinterpret_cast<__nv_bfloat162*>(&a);
    __nv_bfloat162 bv = *reinterpret_cast<__nv_bfloat162*>(&b);
    __nv_bfloat162 z = __float2bfloat162_rn(0.0f);
    __nv_bfloat162 r = __hmax2(__hadd2(av, bv), z);
    return *reinterpret_cast<uint32_t*>(&r);
}
__device__ __forceinline__ void mma_16816(float* c, uint32_t a0, uint32_t a1,
                                          uint32_t a2, uint32_t a3,
                                          uint32_t b0, uint32_t b1) {
    asm volatile(
        "mma.sync.aligned.m16n8k16.row.col.f32.bf16.bf16.f32 "
        "{%0,%1,%2,%3}, {%4,%5,%6,%7}, {%8,%9}, {%0,%1,%2,%3};"
        : "+f"(c[0]), "+f"(c[1]), "+f"(c[2]), "+f"(c[3])
        : "r"(a0), "r"(a1), "r"(a2), "r"(a3), "r"(b0), "r"(b1));
}

// ---------------------------------------------------------------------------
// pre-phase helpers (depth-2 pipeline, R14 form)
// ---------------------------------------------------------------------------
__device__ __forceinline__ void pre_load_tile(
    float4* F0, float4* F1, int t, int rows, bool isA,
    const int* __restrict__ nodes, const float* __restrict__ u2e,
    int g, int tig)
{
    const int r0 = t * 16 + g;
    const int r1 = r0 + 8;
    const int rr0 = r0 < rows ? r0 : rows - 1;
    const int rr1 = r1 < rows ? r1 : rows - 1;
    const int src0 = isA ? rr0 : nodes[rr0];
    const int src1 = isA ? rr1 : nodes[rr1];
    const float4* x0 = (const float4*)(u2e + (size_t)src0 * 64) + tig * 4;
    const float4* x1 = (const float4*)(u2e + (size_t)src1 * 64) + tig * 4;
    #pragma unroll
    for (int q = 0; q < 4; q++) { F0[q] = x0[q]; F1[q] = x1[q]; }
}

// ---------------------------------------------------------------------------
// Fused kernel: phase 1 = pre (preA/preB GEMM + g_starts), device-wide
// barrier, phase 2 = edge (logit GEMM -> g_ex).  Grid MUST be fully
// co-resident: 296 CTAs at 2 CTAs/SM (148 SMs), enforced by launch_bounds.
// ---------------------------------------------------------------------------
__global__ __launch_bounds__(256, 2) void pre_edge_kernel(
    const int* __restrict__ nodes, const int* __restrict__ neigh,
    const int* __restrict__ seg, const float* __restrict__ u2e,
    const float* __restrict__ w1, const float* __restrict__ b1,
    const float* __restrict__ w2, const float* __restrict__ b2,
    const float* __restrict__ w3, const float* __restrict__ b3,
    int V, int N, int E)
{
    __shared__ uint2 s_fragW1[2048];   // W1 frags (both halves, permuted k) 16 KB
    __shared__ uint2 s_fragW2[1024];   // W2 frags (standard layout)          8 KB
    __shared__ float s_b1[64];
    __shared__ float s_b2[64];
    __shared__ float s_w3[64];
    __shared__ float s_b3;

    const int tid  = threadIdx.x;
    const int lane = tid & 31;
    const int wid  = tid >> 5;
    const int g    = lane >> 2;
    const int tig  = lane & 3;

    // g_starts via binary search (overlapped with prologue)
    {
        int gtid = blockIdx.x * 256 + tid;
        if (gtid <= N) {
            if (gtid == N) g_starts[N] = E;
            else {
                int lo = 0, hi = E;
                while (lo < hi) {
                    int mid = (lo + hi) >> 1;
                    if (seg[mid] < gtid) lo = mid + 1; else hi = mid;
                }
                g_starts[gtid] = lo;
            }
        }
    }

    // W1 frag table straight from global (L2-cached), permuted-k layout.
    for (int i = tid; i < 2048; i += 256) {
        int half = i >> 10;
        int rem  = i & 1023;
        int kc   = rem >> 8;
        int nc   = (rem >> 5) & 7;
        int ln   = rem & 31;
        int lg   = ln >> 2, lt = ln & 3;
        int k0 = 16 * lt + 4 * kc;
        int n  = nc * 8 + lg;
        const float* base = w1 + half * 4096;
        uint2 f;
        f.x = pack_bf2(base[k0 * 64 + n],       base[(k0 + 1) * 64 + n]);
        f.y = pack_bf2(base[(k0 + 2) * 64 + n], base[(k0 + 3) * 64 + n]);
        s_fragW1[i] = f;
    }
    // W2 frag table straight from global, STANDARD m16n8k16 layout.
    for (int i = tid; i < 1024; i += 256) {
        int kc = i >> 8;
        int nc = (i >> 5) & 7;
        int ln = i & 31;
        int lg = ln >> 2, lt = ln & 3;
        int k0 = kc * 16 + 2 * lt;
        int n  = nc * 8 + lg;
        uint2 f;
        f.x = pack_bf2(w2[k0 * 64 + n],       w2[(k0 + 1) * 64 + n]);
        f.y = pack_bf2(w2[(k0 + 8) * 64 + n], w2[(k0 + 9) * 64 + n]);
        s_fragW2[i] = f;
    }
    if (tid < 64) { s_b1[tid] = b1[tid]; s_b2[tid] = b2[tid]; s_w3[tid] = w3[tid]; }
    if (tid == 255) s_b3 = b3[0];
    __syncthreads();

    // ===================== phase 1: pre =====================
    {
        const int tA = (V + 15) / 16;
        const int tB = (N + 15) / 16;
        const int nw = gridDim.x * 8;
        const int w  = blockIdx.x * 8 + wid;
        int wA = (int)(((long long)nw * tA) / (tA + tB));
        if (wA < 1) wA = 1;
        if (wA > nw - 1) wA = nw - 1;

        const bool isA   = (w < wA);
        const int tiles  = isA ? tA : tB;
        const int tfirst = isA ? w : (w - wA);
        const int tstep  = isA ? wA : (nw - wA);
        const int rows   = isA ? V : N;
        uint32_t* gout   = isA ? g_preA : g_preB;
        const uint2* frag = s_fragW1 + (isA ? 0 : 1024) + lane;

        if (tfirst < tiles) {
            float4 F0[4], F1[4];
            int r0 = tfirst * 16 + g;
            int r1 = r0 + 8;
            pre_load_tile(F0, F1, tfirst, rows, isA, nodes, u2e, g, tig);

            for (int t = tfirst; t < tiles; t += tstep) {
                uint32_t a0v[4], a1v[4], a2v[4], a3v[4];
                #pragma unroll
                for (int kc = 0; kc < 4; kc++) {
                    a0v[kc] = pack_bf2(F0[kc].x, F0[kc].y);
                    a1v[kc] = pack_bf2(F1[kc].x, F1[kc].y);
                    a2v[kc] = pack_bf2(F0[kc].z, F0[kc].w);
                    a3v[kc] = pack_bf2(F1[kc].z, F1[kc].w);
                }

                const int tn = t + tstep;
                if (tn < tiles)
                    pre_load_tile(F0, F1, tn, rows, isA, nodes, u2e, g, tig);

                float c[8][4];
                #pragma unroll
                for (int nc = 0; nc < 8; nc++) {
                    c[nc][0] = 0.f; c[nc][1] = 0.f; c[nc][2] = 0.f; c[nc][3] = 0.f;
                }
                #pragma unroll
                for (int kc = 0; kc < 4; kc++) {
                    #pragma unroll
                    for (int nc = 0; nc < 8; nc++) {
                        uint2 b = frag[(kc * 8 + nc) * 32];
                        mma_16816(c[nc], a0v[kc], a1v[kc], a2v[kc], a3v[kc], b.x, b.y);
                    }
                }

                uint32_t o0[8], o1[8];
                #pragma unroll
                for (int nc = 0; nc < 8; nc++) {
                    const int col0 = nc * 8 + 2 * tig;
                    const float add0 = isA ? s_b1[col0] : 0.0f;
                    const float add1 = isA ? s_b1[col0 + 1] : 0.0f;
                    o0[nc] = pack_bf2(c[nc][0] + add0, c[nc][1] + add1);
                    o1[nc] = pack_bf2(c[nc][2] + add0, c[nc][3] + add1);
                }
                if (r0 < rows) {
                    uint4* p = (uint4*)(gout + (size_t)r0 * 32 + tig * 8);
                    p[0] = ((uint4*)o0)[0]; p[1] = ((uint4*)o0)[1];
                }
                if (r1 < rows) {
                    uint4* p = (uint4*)(gout + (size_t)r1 * 32 + tig * 8);
                    p[0] = ((uint4*)o1)[0]; p[1] = ((uint4*)o1)[1];
                }
                r0 = tn * 16 + g;
                r1 = r0 + 8;
            }
        }
    }

    // ============ device-wide barrier (monotonic, replay-safe) ============
    __syncthreads();
    if (tid == 0) {
        __threadfence();
        unsigned int old = atomicAdd(&g_bar, 1u);
        unsigned int grid = gridDim.x;
        unsigned int target = (old / grid + 1u) * grid;
        for (;;) {
            unsigned int cur;
            asm volatile("ld.acquire.gpu.global.u32 %0, [%1];"
                         : "=r"(cur) : "l"(&g_bar));
            if (cur >= target) break;
            __nanosleep(100);
        }
        __threadfence();
    }
    __syncthreads();

    // ===================== phase 2: edge =====================
    {
        // Load W2 fragments from smem into registers.
        uint32_t Bf[4][8][2];
        #pragma unroll
        for (int kc = 0; kc < 4; kc++) {
            #pragma unroll
            for (int nc = 0; nc < 8; nc++) {
                uint2 b = s_fragW2[(kc * 8 + nc) * 32 + lane];
                Bf[kc][nc][0] = b.x;
                Bf[kc][nc][1] = b.y;
            }
        }
        const float vb3 = s_b3;

        const int ntiles = (E + 15) / 16;
        const int warp_gid = blockIdx.x * 8 + wid;
        const int nwarps   = gridDim.x * 8;

        for (int tile = warp_gid; tile < ntiles; tile += nwarps) {
            const int base = tile * 16;
            const int e0 = base + g;
            const int e1 = e0 + 8;
            const int ee0 = e0 < E ? e0 : E - 1;
            const int ee1 = e1 < E ? e1 : E - 1;

            const uint4* qa0 = (const uint4*)(g_preA + (size_t)neigh[ee0] * 32) + tig * 2;
            const uint4* qb0 = (const uint4*)(g_preB + (size_t)seg[ee0]  * 32) + tig * 2;
            const uint4* qa1 = (const uint4*)(g_preA + (size_t)neigh[ee1] * 32) + tig * 2;
            const uint4* qb1 = (const uint4*)(g_preB + (size_t)seg[ee1]  * 32) + tig * 2;

            uint4 Aa0 = qa0[0], Ab0 = qa0[1];
            uint4 Ba0 = qb0[0], Bb0 = qb0[1];
            uint4 Aa1 = qa1[0], Ab1 = qa1[1];
            uint4 Ba1 = qb1[0], Bb1 = qb1[1];

            uint32_t r0[8], r1[8];
            r0[0] = hadd_relu2(Aa0.x, Ba0.x); r0[1] = hadd_relu2(Aa0.y, Ba0.y);
            r0[2] = hadd_relu2(Aa0.z, Ba0.z); r0[3] = hadd_relu2(Aa0.w, Ba0.w);
            r0[4] = hadd_relu2(Ab0.x, Bb0.x); r0[5] = hadd_relu2(Ab0.y, Bb0.y);
            r0[6] = hadd_relu2(Ab0.z, Bb0.z); r0[7] = hadd_relu2(Ab0.w, Bb0.w);
            r1[0] = hadd_relu2(Aa1.x, Ba1.x); r1[1] = hadd_relu2(Aa1.y, Ba1.y);
            r1[2] = hadd_relu2(Aa1.z, Ba1.z); r1[3] = hadd_relu2(Aa1.w, Ba1.w);
            r1[4] = hadd_relu2(Ab1.x, Bb1.x); r1[5] = hadd_relu2(Ab1.y, Bb1.y);
            r1[6] = hadd_relu2(Ab1.z, Bb1.z); r1[7] = hadd_relu2(Ab1.w, Bb1.w);

            float c[8][4];
            #pragma unroll
            for (int nc = 0; nc < 8; nc++) {
                c[nc][0] = 0.f; c[nc][1] = 0.f; c[nc][2] = 0.f; c[nc][3] = 0.f;
            }
            #pragma unroll
            for (int kc = 0; kc < 4; kc++) {
                uint32_t a0 = r0[2 * kc],     a2 = r0[2 * kc + 1];
                uint32_t a1 = r1[2 * kc],     a3 = r1[2 * kc + 1];
                #pragma unroll
                for (int nc = 0; nc < 8; nc++)
                    mma_16816(c[nc], a0, a1, a2, a3, Bf[kc][nc][0], Bf[kc][nc][1]);
            }

            float p0 = 0.f, p1 = 0.f;
            #pragma unroll
            for (int nc = 0; nc < 8; nc++) {
                const int col0 = nc * 8 + 2 * tig;
                const int col1 = col0 + 1;
                const float bb0 = s_b2[col0], bb1 = s_b2[col1];
                const float ww0 = s_w3[col0], ww1 = s_w3[col1];
                p0 = fmaf(fmaxf(c[nc][0] + bb0, 0.f), ww0, p0);
                p0 = fmaf(fmaxf(c[nc][1] + bb1, 0.f), ww1, p0);
                p1 = fmaf(fmaxf(c[nc][2] + bb0, 0.f), ww0, p1);
                p1 = fmaf(fmaxf(c[nc][3] + bb1, 0.f), ww1, p1);
            }
            p0 += __shfl_xor_sync(0xffffffffu, p0, 1);
            p0 += __shfl_xor_sync(0xffffffffu, p0, 2);
            p1 += __shfl_xor_sync(0xffffffffu, p1, 1);
            p1 += __shfl_xor_sync(0xffffffffu, p1, 2);

            if (tig == 0) {
                if (e0 < E) g_ex[e0] = __expf(p0 + vb3);
                if (e1 < E) g_ex[e1] = __expf(p1 + vb3);
            }
        }
    }
}

// ---------------------------------------------------------------------------
// Kernel 2: warp-per-node normalize + attention-weighted sum.  (R14 form)
// ---------------------------------------------------------------------------
__global__ void agg_kernel(const int* __restrict__ neigh,
                           const float* __restrict__ u2e,
                           float* __restrict__ out, int N, int E)
{
    int gw   = (blockIdx.x * blockDim.x + threadIdx.x) >> 5;
    int lane = threadIdx.x & 31;
    if (gw >= N) return;

    int s    = g_starts[gw];
    int epos = g_starts[gw + 1];

    float sum = 0.0f;
    for (int i = s + lane; i < epos; i += 32) sum += g_ex[i];
    #pragma unroll
    for (int o = 16; o; o >>= 1) sum += __shfl_xor_sync(0xffffffffu, sum, o);
    float inv = 1.0f / fmaxf(sum, 1e-9f);

    const int half = lane >> 4;
    const int qc   = lane & 15;
    float4 acc0 = make_float4(0.f, 0.f, 0.f, 0.f);
    float4 acc1 = make_float4(0.f, 0.f, 0.f, 0.f);
    int i = s + half;
    for (; i + 2 < epos; i += 4) {
        float att0 = g_ex[i] * inv;
        float att1 = g_ex[i + 2] * inv;
        float4 v0 = ((const float4*)(u2e + (size_t)neigh[i] * 64))[qc];
        float4 v1 = ((const float4*)(u2e + (size_t)neigh[i + 2] * 64))[qc];
        acc0.x = fmaf(att0, v0.x, acc0.x);
        acc0.y = fmaf(att0, v0.y, acc0.y);
        acc0.z = fmaf(att0, v0.z, acc0.z);
        acc0.w = fmaf(att0, v0.w, acc0.w);
        acc1.x = fmaf(att1, v1.x, acc1.x);
        acc1.y = fmaf(att1, v1.y, acc1.y);
        acc1.z = fmaf(att1, v1.z, acc1.z);
        acc1.w = fmaf(att1, v1.w, acc1.w);
    }
    if (i < epos) {
        float att = g_ex[i] * inv;
        float4 v = ((const float4*)(u2e + (size_t)neigh[i] * 64))[qc];
        acc0.x = fmaf(att, v.x, acc0.x);
        acc0.y = fmaf(att, v.y, acc0.y);
        acc0.z = fmaf(att, v.z, acc0.z);
        acc0.w = fmaf(att, v.w, acc0.w);
    }
    acc0.x += acc1.x; acc0.y += acc1.y; acc0.z += acc1.z; acc0.w += acc1.w;
    acc0.x += __shfl_xor_sync(0xffffffffu, acc0.x, 16);
    acc0.y += __shfl_xor_sync(0xffffffffu, acc0.y, 16);
    acc0.z += __shfl_xor_sync(0xffffffffu, acc0.z, 16);
    acc0.w += __shfl_xor_sync(0xffffffffu, acc0.w, 16);
    if (lane < 16)
        ((float4*)out)[(size_t)gw * 16 + qc] = acc0;
}

// ---------------------------------------------------------------------------
extern "C" void kernel_launch(void* const* d_in, const int* in_sizes, int n_in,
                              void* d_out, int out_size)
{
    const int*   nodes = (const int*)d_in[0];
    const int*   neigh = (const int*)d_in[1];
    const int*   seg   = (const int*)d_in[2];
    const float* u2e   = (const float*)d_in[3];
    const float* w1    = (const float*)d_in[4];
    const float* b1    = (const float*)d_in[5];
    const float* w2    = (const float*)d_in[6];
    const float* b2    = (const float*)d_in[7];
    const float* w3    = (const float*)d_in[8];
    const float* b3    = (const float*)d_in[9];

    int N = in_sizes[0];
    int E = in_sizes[1];
    int V = in_sizes[3] / 64;
    if (E > CAP_E) E = CAP_E;
    if (N > CAP_N - 2) N = CAP_N - 2;
    if (V > CAP_V) V = CAP_V;

    // Grid must be fully co-resident for the device-wide barrier:
    // 296 = 148 SMs x 2 CTAs/SM (enforced by __launch_bounds__(256, 2)).
    pre_edge_kernel<<<296, 256>>>(nodes, neigh, seg, u2e,
                                  w1, b1, w2, b2, w3, b3, V, N, E);

    agg_kernel<<<(N * 32 + 255) / 256, 256>>>(neigh, u2e, (float*)d_out, N, E);
}